// round 1
// baseline (speedup 1.0000x reference)
#include <cuda_runtime.h>
#include <math.h>

// Problem dims (compile-time constants)
#define L_  8
#define B_  8
#define S_  2048
#define D_  1024
#define H_  16
#define DH_ 64
#define F_  4096

// ---------------------------------------------------------------------------
// Scratch buffers: __device__ globals (allocation-guard-safe).
// ---------------------------------------------------------------------------
__device__ float g_h   [(size_t)B_ * S_ * D_];   // LN1/LN2 output
__device__ float g_q   [(size_t)B_ * S_ * D_];
__device__ float g_k   [(size_t)B_ * S_ * D_];
__device__ float g_v   [(size_t)B_ * S_ * D_];
__device__ float g_attn[(size_t)B_ * S_ * D_];   // attention output (pre-Wo)
__device__ float g_ffn [(size_t)B_ * S_ * F_];   // FFN hidden

// ---------------------------------------------------------------------------
// LayerNorm: one block per (b,s) row of D=1024. 256 threads, 1 float4 each.
// ---------------------------------------------------------------------------
__global__ __launch_bounds__(256) void ln_kernel(
    const float* __restrict__ X,
    const float* __restrict__ sall,   // [L, D]
    const float* __restrict__ ball,   // [L, D]
    const int*   __restrict__ lidx,   // [B]
    float* __restrict__ Y)
{
    int row = blockIdx.x;             // 0 .. B*S-1
    int b   = row / S_;
    int tid = threadIdx.x;

    const float4* xr = (const float4*)(X + (size_t)row * D_);
    float4 xv = xr[tid];

    float s  = xv.x + xv.y + xv.z + xv.w;
    float ss = xv.x*xv.x + xv.y*xv.y + xv.z*xv.z + xv.w*xv.w;

    #pragma unroll
    for (int o = 16; o > 0; o >>= 1) {
        s  += __shfl_xor_sync(0xffffffffu, s,  o);
        ss += __shfl_xor_sync(0xffffffffu, ss, o);
    }
    __shared__ float rs[8], rss[8];
    __shared__ float mv[2];
    int wid = tid >> 5, lane = tid & 31;
    if (lane == 0) { rs[wid] = s; rss[wid] = ss; }
    __syncthreads();
    if (tid == 0) {
        float a = 0.f, c = 0.f;
        #pragma unroll
        for (int w = 0; w < 8; w++) { a += rs[w]; c += rss[w]; }
        float mean = a * (1.0f / D_);
        float var  = c * (1.0f / D_) - mean * mean;
        mv[0] = mean;
        mv[1] = rsqrtf(var + 1e-5f);
    }
    __syncthreads();
    float mean = mv[0], rstd = mv[1];

    int li = lidx[b];
    float4 sv = ((const float4*)(sall + (size_t)li * D_))[tid];
    float4 bv = ((const float4*)(ball + (size_t)li * D_))[tid];

    float4 o;
    o.x = (xv.x - mean) * rstd * sv.x + bv.x;
    o.y = (xv.y - mean) * rstd * sv.y + bv.y;
    o.z = (xv.z - mean) * rstd * sv.z + bv.z;
    o.w = (xv.w - mean) * rstd * sv.w + bv.w;
    ((float4*)(Y + (size_t)row * D_))[tid] = o;
}

// ---------------------------------------------------------------------------
// GELU (tanh approximation — matches jax.nn.gelu default approximate=True)
// ---------------------------------------------------------------------------
__device__ __forceinline__ float gelu_f(float x)
{
    float t = 0.7978845608028654f * (x + 0.044715f * x * x * x);
    float th;
    asm("tanh.approx.f32 %0, %1;" : "=f"(th) : "f"(t));
    return 0.5f * x * (1.0f + th);
}

// ---------------------------------------------------------------------------
// Routed-weight SGEMM: C[b] = A[b](MxK) @ W[lidx[b]](KxN) + bias[lidx[b]]
//                      (+ optional residual, + optional GELU)
// 128x128x16 block tile, 8x8 microtile (split-64 mapping, float4 smem reads).
// ---------------------------------------------------------------------------
template <int ACT, int RES>
__global__ __launch_bounds__(256) void gemm_kernel(
    const float* __restrict__ A,
    const float* __restrict__ Wall,    // [L, K, N]
    const float* __restrict__ biasall, // [L, N]
    const int*   __restrict__ lidx,    // [B]
    const float* __restrict__ Res,     // [B, M, N] or nullptr
    float* __restrict__ C,             // [B, M, N]
    int M, int K, int N)
{
    constexpr int BM = 128, BN = 128, BK = 16;
    __shared__ float As[BK][BM];   // transposed A tile
    __shared__ float Bs[BK][BN];

    int b  = blockIdx.z;
    int li = lidx[b];
    const float* W    = Wall    + (size_t)li * K * N;
    const float* bias = biasall + (size_t)li * N;
    const float* Ab   = A       + (size_t)b * M * K;
    float*       Cb   = C       + (size_t)b * M * N;

    int row0 = blockIdx.y * BM;
    int col0 = blockIdx.x * BN;
    int tid  = threadIdx.x;
    int tx   = tid & 15;     // 0..15
    int ty   = tid >> 4;     // 0..15

    float acc[8][8];
    #pragma unroll
    for (int i = 0; i < 8; i++)
        #pragma unroll
        for (int j = 0; j < 8; j++) acc[i][j] = 0.f;

    for (int k0 = 0; k0 < K; k0 += BK) {
        #pragma unroll
        for (int p = 0; p < 2; p++) {
            int it = tid + p * 256;
            // A tile: 128 rows x 16 cols = 512 float4
            int arow = it >> 2;
            int ak   = (it & 3) * 4;
            float4 av = *(const float4*)&Ab[(size_t)(row0 + arow) * K + k0 + ak];
            As[ak + 0][arow] = av.x;
            As[ak + 1][arow] = av.y;
            As[ak + 2][arow] = av.z;
            As[ak + 3][arow] = av.w;
            // B tile: 16 rows x 128 cols = 512 float4
            int brow = it >> 5;
            int bc   = (it & 31) * 4;
            float4 bv = *(const float4*)&W[(size_t)(k0 + brow) * N + col0 + bc];
            *(float4*)&Bs[brow][bc] = bv;
        }
        __syncthreads();

        #pragma unroll
        for (int kk = 0; kk < BK; kk++) {
            float af[8], bf[8];
            *(float4*)&af[0] = *(float4*)&As[kk][ty * 4];
            *(float4*)&af[4] = *(float4*)&As[kk][ty * 4 + 64];
            *(float4*)&bf[0] = *(float4*)&Bs[kk][tx * 4];
            *(float4*)&bf[4] = *(float4*)&Bs[kk][tx * 4 + 64];
            #pragma unroll
            for (int i = 0; i < 8; i++)
                #pragma unroll
                for (int j = 0; j < 8; j++)
                    acc[i][j] += af[i] * bf[j];
        }
        __syncthreads();
    }

    // Epilogue: rows = ty*4 + {0..3} and 64+ty*4+{0..3}; cols likewise on tx.
    #pragma unroll
    for (int i = 0; i < 8; i++) {
        int r = row0 + ((i < 4) ? (ty * 4 + i) : (64 + ty * 4 + (i - 4)));
        #pragma unroll
        for (int jz = 0; jz < 2; jz++) {
            int c = col0 + tx * 4 + jz * 64;
            float4 rv;
            if (RES) rv = *(const float4*)&Res[(size_t)b * M * N + (size_t)r * N + c];
            float4 o;
            float* op = &o.x;
            const float* rp = &rv.x;
            #pragma unroll
            for (int w = 0; w < 4; w++) {
                int j = jz * 4 + w;
                float val = acc[i][j] + bias[c + w];
                if (ACT == 1) val = gelu_f(val);
                if (RES) val += rp[w];
                op[w] = val;
            }
            *(float4*)&Cb[(size_t)r * N + c] = o;
        }
    }
}

// ---------------------------------------------------------------------------
// Flash attention (non-causal, full softmax over S), fp32.
// One block per (b, h, 128-q-row tile). 256 threads.
// 8x4 microtile (rows ty+16i, cols tx+16j). Online softmax.
// ---------------------------------------------------------------------------
#define AT_SMEM_FLOATS (128*65 + 64*65 + 64*64 + 128*65)
#define AT_SMEM_BYTES  (AT_SMEM_FLOATS * 4)

__global__ __launch_bounds__(256) void attention_kernel(
    const float* __restrict__ Q,
    const float* __restrict__ K,
    const float* __restrict__ V,
    float* __restrict__ O)
{
    extern __shared__ float sm[];
    float* Qs = sm;                        // [128][65]
    float* Ks = Qs + 128 * 65;             // [64][65]
    float* Vs = Ks + 64 * 65;              // [64][64]
    float* Ps = Vs + 64 * 64;              // [128][65]

    int q0 = blockIdx.x * 128;
    int hh = blockIdx.y;
    int b  = blockIdx.z;
    int tid = threadIdx.x;
    int tx  = tid & 15;
    int ty  = tid >> 4;

    size_t base = (size_t)b * S_ * D_ + (size_t)hh * DH_;

    // Load Q tile, pre-scaled by 1/sqrt(DH)=0.125
    for (int it = tid; it < 128 * 16; it += 256) {
        int r  = it >> 4;
        int c4 = (it & 15) * 4;
        float4 qv = *(const float4*)&Q[base + (size_t)(q0 + r) * D_ + c4];
        float* dst = &Qs[r * 65 + c4];
        dst[0] = qv.x * 0.125f; dst[1] = qv.y * 0.125f;
        dst[2] = qv.z * 0.125f; dst[3] = qv.w * 0.125f;
    }

    float m_run[8], l_run[8], oacc[8][4];
    #pragma unroll
    for (int i = 0; i < 8; i++) {
        m_run[i] = -1e30f;
        l_run[i] = 0.f;
        #pragma unroll
        for (int j = 0; j < 4; j++) oacc[i][j] = 0.f;
    }

    for (int t = 0; t < S_ / 64; t++) {
        int k0 = t * 64;
        // Load K,V tiles
        for (int it = tid; it < 64 * 16; it += 256) {
            int r  = it >> 4;
            int c4 = (it & 15) * 4;
            float4 kv = *(const float4*)&K[base + (size_t)(k0 + r) * D_ + c4];
            float* dk = &Ks[r * 65 + c4];
            dk[0] = kv.x; dk[1] = kv.y; dk[2] = kv.z; dk[3] = kv.w;
            float4 vv = *(const float4*)&V[base + (size_t)(k0 + r) * D_ + c4];
            *(float4*)&Vs[r * 64 + c4] = vv;
        }
        __syncthreads();   // also covers Q on first iteration

        // S tile = Qs @ Ks^T (already scaled)
        float sreg[8][4];
        #pragma unroll
        for (int i = 0; i < 8; i++)
            #pragma unroll
            for (int j = 0; j < 4; j++) sreg[i][j] = 0.f;

        #pragma unroll 8
        for (int k = 0; k < 64; k++) {
            float qv[8], kv[4];
            #pragma unroll
            for (int i = 0; i < 8; i++) qv[i] = Qs[(ty + 16 * i) * 65 + k];
            #pragma unroll
            for (int j = 0; j < 4; j++) kv[j] = Ks[(tx + 16 * j) * 65 + k];
            #pragma unroll
            for (int i = 0; i < 8; i++)
                #pragma unroll
                for (int j = 0; j < 4; j++)
                    sreg[i][j] += qv[i] * kv[j];
        }

        // Online softmax (row reduce across the 16 tx lanes)
        #pragma unroll
        for (int i = 0; i < 8; i++) {
            float mt = fmaxf(fmaxf(sreg[i][0], sreg[i][1]),
                             fmaxf(sreg[i][2], sreg[i][3]));
            #pragma unroll
            for (int o = 8; o > 0; o >>= 1)
                mt = fmaxf(mt, __shfl_xor_sync(0xffffffffu, mt, o));
            float mn   = fmaxf(m_run[i], mt);
            float corr = __expf(m_run[i] - mn);
            float ps = 0.f;
            #pragma unroll
            for (int j = 0; j < 4; j++) {
                float p = __expf(sreg[i][j] - mn);
                Ps[(ty + 16 * i) * 65 + tx + 16 * j] = p;
                ps += p;
            }
            #pragma unroll
            for (int o = 8; o > 0; o >>= 1)
                ps += __shfl_xor_sync(0xffffffffu, ps, o);
            l_run[i] = l_run[i] * corr + ps;
            m_run[i] = mn;
            #pragma unroll
            for (int j = 0; j < 4; j++) oacc[i][j] *= corr;
        }
        __syncthreads();

        // O += P @ V
        #pragma unroll 8
        for (int c = 0; c < 64; c++) {
            float pv[8], vv[4];
            #pragma unroll
            for (int i = 0; i < 8; i++) pv[i] = Ps[(ty + 16 * i) * 65 + c];
            #pragma unroll
            for (int j = 0; j < 4; j++) vv[j] = Vs[c * 64 + tx + 16 * j];
            #pragma unroll
            for (int i = 0; i < 8; i++)
                #pragma unroll
                for (int j = 0; j < 4; j++)
                    oacc[i][j] += pv[i] * vv[j];
        }
        __syncthreads();
    }

    // Normalize and write out
    #pragma unroll
    for (int i = 0; i < 8; i++) {
        float inv = 1.0f / l_run[i];
        int r = q0 + ty + 16 * i;
        #pragma unroll
        for (int j = 0; j < 4; j++)
            O[base + (size_t)r * D_ + tx + 16 * j] = oacc[i][j] * inv;
    }
}

// ---------------------------------------------------------------------------
// Launch: LN1 -> QKV -> attention -> O-proj(+res) -> LN2 -> FFN1(gelu) ->
//         FFN2(+res). All on the default stream (graph-capturable).
// ---------------------------------------------------------------------------
extern "C" void kernel_launch(void* const* d_in, const int* in_sizes, int n_in,
                              void* d_out, int out_size)
{
    (void)in_sizes; (void)n_in; (void)out_size;
    const float* x    = (const float*)d_in[0];
    const int*   lidx = (const int*)  d_in[1];
    const float* Wq = (const float*)d_in[2];  const float* bq = (const float*)d_in[3];
    const float* Wk = (const float*)d_in[4];  const float* bk = (const float*)d_in[5];
    const float* Wv = (const float*)d_in[6];  const float* bv = (const float*)d_in[7];
    const float* Wo = (const float*)d_in[8];  const float* bo = (const float*)d_in[9];
    const float* s1 = (const float*)d_in[10]; const float* b1n = (const float*)d_in[11];
    const float* s2 = (const float*)d_in[12]; const float* b2n = (const float*)d_in[13];
    const float* W1 = (const float*)d_in[14]; const float* bf1 = (const float*)d_in[15];
    const float* W2 = (const float*)d_in[16]; const float* bf2 = (const float*)d_in[17];
    float* out = (float*)d_out;

    float *h_, *q_, *k_, *v_, *at_, *ff_;
    cudaGetSymbolAddress((void**)&h_,  g_h);
    cudaGetSymbolAddress((void**)&q_,  g_q);
    cudaGetSymbolAddress((void**)&k_,  g_k);
    cudaGetSymbolAddress((void**)&v_,  g_v);
    cudaGetSymbolAddress((void**)&at_, g_attn);
    cudaGetSymbolAddress((void**)&ff_, g_ffn);

    cudaFuncSetAttribute(attention_kernel,
                         cudaFuncAttributeMaxDynamicSharedMemorySize,
                         AT_SMEM_BYTES);

    dim3 gD(D_ / 128, S_ / 128, B_);   // N=1024 GEMMs
    dim3 gF(F_ / 128, S_ / 128, B_);   // N=4096 GEMM (FFN1)

    // LN1
    ln_kernel<<<B_ * S_, 256>>>(x, s1, b1n, lidx, h_);
    // Q, K, V projections
    gemm_kernel<0, 0><<<gD, 256>>>(h_, Wq, bq, lidx, nullptr, q_, S_, D_, D_);
    gemm_kernel<0, 0><<<gD, 256>>>(h_, Wk, bk, lidx, nullptr, k_, S_, D_, D_);
    gemm_kernel<0, 0><<<gD, 256>>>(h_, Wv, bv, lidx, nullptr, v_, S_, D_, D_);
    // Attention
    attention_kernel<<<dim3(S_ / 128, H_, B_), 256, AT_SMEM_BYTES>>>(q_, k_, v_, at_);
    // Output projection + residual (x)  -> out holds x_mid
    gemm_kernel<0, 1><<<gD, 256>>>(at_, Wo, bo, lidx, x, out, S_, D_, D_);
    // LN2 on x_mid
    ln_kernel<<<B_ * S_, 256>>>(out, s2, b2n, lidx, h_);
    // FFN1 + GELU
    gemm_kernel<1, 0><<<gF, 256>>>(h_, W1, bf1, lidx, nullptr, ff_, S_, D_, F_);
    // FFN2 + residual (x_mid) -> final output
    gemm_kernel<0, 1><<<gD, 256>>>(ff_, W2, bf2, lidx, out, out, S_, F_, D_);
}

// round 3
// speedup vs baseline: 1.8992x; 1.8992x over previous
#include <cuda_runtime.h>
#include <math.h>
#include <stdint.h>

// Problem dims
#define L_  8
#define B_  8
#define S_  2048
#define D_  1024
#define H_  16
#define DH_ 64
#define F_  4096

// ---------------------------------------------------------------------------
// Scratch (__device__ globals; allocation-guard-safe)
// ---------------------------------------------------------------------------
__device__ float g_h   [(size_t)B_ * S_ * D_];
__device__ float g_q   [(size_t)B_ * S_ * D_];
__device__ float g_k   [(size_t)B_ * S_ * D_];
__device__ float g_v   [(size_t)B_ * S_ * D_];
__device__ float g_attn[(size_t)B_ * S_ * D_];
__device__ float g_ffn [(size_t)B_ * S_ * F_];
// Transposed + tf32-rounded weights: Wt[l][n][k]
__device__ float g_WqT[(size_t)L_ * D_ * D_];
__device__ float g_WkT[(size_t)L_ * D_ * D_];
__device__ float g_WvT[(size_t)L_ * D_ * D_];
__device__ float g_WoT[(size_t)L_ * D_ * D_];
__device__ float g_W1T[(size_t)L_ * D_ * F_];
__device__ float g_W2T[(size_t)L_ * F_ * D_];

// ---------------------------------------------------------------------------
// Helpers (baseline PTX only — no 'a'-suffix accel features)
// ---------------------------------------------------------------------------
__device__ __forceinline__ uint32_t smem_u32(const void* p) {
    uint32_t a;
    asm("{ .reg .u64 t; cvta.to.shared.u64 t, %1; cvt.u32.u64 %0, t; }"
        : "=r"(a) : "l"(p));
    return a;
}

__device__ __forceinline__ float tf32r(float x) {   // round-to-nearest tf32
    uint32_t u;
    asm("cvt.rna.tf32.f32 %0, %1;" : "=r"(u) : "f"(x));
    return __uint_as_float(u);
}

#define SMEM_SWZ128(o) ((o) ^ (((o) >> 3) & 0x70))

#define CP_ASYNC16(dst_u32, src_ptr) \
    asm volatile("cp.async.cg.shared.global [%0], [%1], 16;" \
                 :: "r"(dst_u32), "l"(src_ptr))
#define CP_ASYNC_COMMIT() asm volatile("cp.async.commit_group;" ::: "memory")
#define CP_ASYNC_WAIT1()  asm volatile("cp.async.wait_group 1;" ::: "memory")
#define CP_ASYNC_WAIT0()  asm volatile("cp.async.wait_group 0;" ::: "memory")

__device__ __forceinline__ void ldsm_x4(uint32_t (&r)[4], uint32_t addr) {
    asm volatile("ldmatrix.sync.aligned.m8n8.x4.shared.b16 {%0,%1,%2,%3}, [%4];"
                 : "=r"(r[0]), "=r"(r[1]), "=r"(r[2]), "=r"(r[3]) : "r"(addr));
}

__device__ __forceinline__ void mma_tf32(float (&d)[4],
                                         const uint32_t (&a)[4],
                                         uint32_t b0, uint32_t b1) {
    asm volatile(
        "mma.sync.aligned.m16n8k8.row.col.f32.tf32.tf32.f32 "
        "{%0,%1,%2,%3}, {%4,%5,%6,%7}, {%8,%9}, {%0,%1,%2,%3};"
        : "+f"(d[0]), "+f"(d[1]), "+f"(d[2]), "+f"(d[3])
        : "r"(a[0]), "r"(a[1]), "r"(a[2]), "r"(a[3]), "r"(b0), "r"(b1));
}

// ---------------------------------------------------------------------------
// GELU (tanh approx — matches jax.nn.gelu default)
// ---------------------------------------------------------------------------
__device__ __forceinline__ float gelu_f(float x)
{
    float t = 0.7978845608028654f * (x + 0.044715f * x * x * x);
    float th;
    asm("tanh.approx.f32 %0, %1;" : "=f"(th) : "f"(t));
    return 0.5f * x * (1.0f + th);
}

// ---------------------------------------------------------------------------
// Weight transpose + tf32 RN round: W[l][K][N] -> Wt[l][N][K]
// ---------------------------------------------------------------------------
__global__ __launch_bounds__(256) void transpose_round_kernel(
    const float* __restrict__ W, float* __restrict__ Wt, int Kd, int Nd)
{
    __shared__ float t[32][33];
    int l  = blockIdx.z;
    int n0 = blockIdx.x * 32;
    int k0 = blockIdx.y * 32;
    const float* Wl  = W  + (size_t)l * Kd * Nd;
    float*       Wtl = Wt + (size_t)l * Nd * Kd;
    int c = threadIdx.x, r0 = threadIdx.y;
    #pragma unroll
    for (int i = 0; i < 4; i++) {
        int r = r0 + i * 8;
        t[r][c] = Wl[(size_t)(k0 + r) * Nd + n0 + c];
    }
    __syncthreads();
    #pragma unroll
    for (int i = 0; i < 4; i++) {
        int r = r0 + i * 8;
        Wtl[(size_t)(n0 + r) * Kd + k0 + c] = tf32r(t[c][r]);
    }
}

// ---------------------------------------------------------------------------
// LayerNorm (rounds output to tf32 — feeds tensor-core GEMMs)
// ---------------------------------------------------------------------------
__global__ __launch_bounds__(256) void ln_kernel(
    const float* __restrict__ X,
    const float* __restrict__ sall, const float* __restrict__ ball,
    const int* __restrict__ lidx, float* __restrict__ Y)
{
    int row = blockIdx.x;
    int b   = row / S_;
    int tid = threadIdx.x;

    float4 xv = ((const float4*)(X + (size_t)row * D_))[tid];
    float s  = xv.x + xv.y + xv.z + xv.w;
    float ss = xv.x*xv.x + xv.y*xv.y + xv.z*xv.z + xv.w*xv.w;
    #pragma unroll
    for (int o = 16; o > 0; o >>= 1) {
        s  += __shfl_xor_sync(0xffffffffu, s,  o);
        ss += __shfl_xor_sync(0xffffffffu, ss, o);
    }
    __shared__ float rs[8], rss[8], mv[2];
    int wid = tid >> 5, lane = tid & 31;
    if (lane == 0) { rs[wid] = s; rss[wid] = ss; }
    __syncthreads();
    if (tid == 0) {
        float a = 0.f, c = 0.f;
        #pragma unroll
        for (int w = 0; w < 8; w++) { a += rs[w]; c += rss[w]; }
        float mean = a * (1.0f / D_);
        float var  = c * (1.0f / D_) - mean * mean;
        mv[0] = mean; mv[1] = rsqrtf(var + 1e-5f);
    }
    __syncthreads();
    float mean = mv[0], rstd = mv[1];

    int li = lidx[b];
    float4 sv = ((const float4*)(sall + (size_t)li * D_))[tid];
    float4 bv = ((const float4*)(ball + (size_t)li * D_))[tid];
    float4 o;
    o.x = tf32r((xv.x - mean) * rstd * sv.x + bv.x);
    o.y = tf32r((xv.y - mean) * rstd * sv.y + bv.y);
    o.z = tf32r((xv.z - mean) * rstd * sv.z + bv.z);
    o.w = tf32r((xv.w - mean) * rstd * sv.w + bv.w);
    ((float4*)(Y + (size_t)row * D_))[tid] = o;
}

// ---------------------------------------------------------------------------
// mma.sync tf32 GEMM: C[b] = A[b](MxK) @ Wt[lidx[b]](NxK)^T + bias
//                     (+GELU) (+residual) (+tf32 round on store)
// 128x128 tile, BK=32, 8 warps (2x4), warp tile 64x32 of m16n8k8.
// 3-stage cp.async ring, SW128 swizzle, ldmatrix fragment loads.
// ---------------------------------------------------------------------------
#define GEMM_SMEM (1024 + 3 * 32768)

template <int ACT, int RES, int RND>
__global__ __launch_bounds__(256, 2)
void gemm_mma(const float* __restrict__ A, const float* __restrict__ WT,
              const float* __restrict__ biasall, const int* __restrict__ lidx,
              const float* __restrict__ Res, float* __restrict__ C,
              int M, int K, int N)
{
    extern __shared__ __align__(16) char smraw[];
    uint32_t sbase = (smem_u32(smraw) + 1023u) & ~1023u;

    int tid  = threadIdx.x;
    int wid  = tid >> 5;
    int lane = tid & 31;
    int wm   = wid >> 2;      // 0..1
    int wn   = wid & 3;       // 0..3
    int b    = blockIdx.z;
    int li   = lidx[b];
    int row0 = blockIdx.y * 128;
    int col0 = blockIdx.x * 128;

    const float* Ag = A  + (size_t)b  * M * K + (size_t)row0 * K;
    const float* Bg = WT + (size_t)li * N * K + (size_t)col0 * K;

    float acc[4][4][4];
    #pragma unroll
    for (int i = 0; i < 4; i++)
        #pragma unroll
        for (int j = 0; j < 4; j++)
            #pragma unroll
            for (int q = 0; q < 4; q++) acc[i][j][q] = 0.f;

    // Per-thread cp.async slots: A and B tiles are each 128 rows x 128B.
    int lrow = tid >> 1;              // 0..127
    int lkb  = (tid & 1) * 64;        // 0 or 64 bytes; 2 chunks of 16B each... 
    // Simpler: 1024 16B-chunks per tile, 4 per thread.
    auto load_stage = [&](int kc, int stg) {
        uint32_t sA = sbase + (uint32_t)stg * 32768u;
        uint32_t sB = sA + 16384u;
        const float* Ak = Ag + kc * 32;
        const float* Bk = Bg + kc * 32;
        #pragma unroll
        for (int p = 0; p < 4; p++) {
            int idx = tid + p * 256;
            int r  = idx >> 3;
            int kb = (idx & 7) * 16;            // byte offset in row
            uint32_t sw = SMEM_SWZ128((uint32_t)(r * 128 + kb));
            CP_ASYNC16(sA + sw, Ak + (size_t)r * K + (kb >> 2));
            CP_ASYNC16(sB + sw, Bk + (size_t)r * K + (kb >> 2));
        }
        CP_ASYNC_COMMIT();
    };

    int nk = K >> 5;
    load_stage(0, 0);
    load_stage(1, 1);

    int lr = lane & 15;      // row-within-16 for ldmatrix addressing
    int lh = (lane >> 4) * 16;  // +16B for second k-half

    for (int i = 0; i < nk; i++) {
        if (i < nk - 2) CP_ASYNC_WAIT1(); else CP_ASYNC_WAIT0();
        __syncthreads();
        if (i + 2 < nk) load_stage(i + 2, (i + 2) % 3);

        uint32_t sA = sbase + (uint32_t)(i % 3) * 32768u;
        uint32_t sB = sA + 16384u;

        #pragma unroll
        for (int ks = 0; ks < 4; ks++) {
            uint32_t afr[4][4];
            uint32_t bfr[2][4];
            #pragma unroll
            for (int mf = 0; mf < 4; mf++) {
                uint32_t off = (uint32_t)((64 * wm + 16 * mf + lr) * 128
                                          + ks * 32 + lh);
                ldsm_x4(afr[mf], sA + SMEM_SWZ128(off));
            }
            #pragma unroll
            for (int bf = 0; bf < 2; bf++) {
                uint32_t off = (uint32_t)((32 * wn + 16 * bf + lr) * 128
                                          + ks * 32 + lh);
                ldsm_x4(bfr[bf], sB + SMEM_SWZ128(off));
            }
            // bfr[bf]: r0=b0(nf=2bf), r1=b0(nf=2bf+1), r2=b1(nf=2bf), r3=b1(nf=2bf+1)
            #pragma unroll
            for (int mf = 0; mf < 4; mf++)
                #pragma unroll
                for (int nf = 0; nf < 4; nf++)
                    mma_tf32(acc[mf][nf], afr[mf],
                             bfr[nf >> 1][nf & 1], bfr[nf >> 1][2 + (nf & 1)]);
        }
    }
    (void)lrow; (void)lkb;

    // Epilogue: c0,c1 at (row=qr, col=qc..qc+1), c2,c3 at row+8.
    int qr = lane >> 2;
    int qc = (lane & 3) * 2;
    const float* bp = biasall + (size_t)li * N;
    #pragma unroll
    for (int mf = 0; mf < 4; mf++) {
        int r = row0 + 64 * wm + 16 * mf + qr;
        #pragma unroll
        for (int nf = 0; nf < 4; nf++) {
            int cc = col0 + 32 * wn + 8 * nf + qc;
            #pragma unroll
            for (int half = 0; half < 2; half++) {
                int rr = r + half * 8;
                float v0 = acc[mf][nf][half * 2 + 0] + bp[cc + 0];
                float v1 = acc[mf][nf][half * 2 + 1] + bp[cc + 1];
                if (ACT) { v0 = gelu_f(v0); v1 = gelu_f(v1); }
                if (RES) {
                    const float* rp = Res + (size_t)b * M * N + (size_t)rr * N + cc;
                    v0 += rp[0]; v1 += rp[1];
                }
                if (RND) { v0 = tf32r(v0); v1 = tf32r(v1); }
                float2 o2 = make_float2(v0, v1);
                *(float2*)&C[(size_t)b * M * N + (size_t)rr * N + cc] = o2;
            }
        }
    }
}

// ---------------------------------------------------------------------------
// Flash attention (fp32 SIMT — unchanged from the passing R1 version,
// plus tf32-rounded output store since it feeds the Wo GEMM)
// ---------------------------------------------------------------------------
#define AT_SMEM_FLOATS (128*65 + 64*65 + 64*64 + 128*65)
#define AT_SMEM_BYTES  (AT_SMEM_FLOATS * 4)

__global__ __launch_bounds__(256) void attention_kernel(
    const float* __restrict__ Q, const float* __restrict__ K,
    const float* __restrict__ V, float* __restrict__ O)
{
    extern __shared__ float sm[];
    float* Qs = sm;
    float* Ks = Qs + 128 * 65;
    float* Vs = Ks + 64 * 65;
    float* Ps = Vs + 64 * 64;

    int q0 = blockIdx.x * 128;
    int hh = blockIdx.y;
    int b  = blockIdx.z;
    int tid = threadIdx.x;
    int tx  = tid & 15;
    int ty  = tid >> 4;

    size_t base = (size_t)b * S_ * D_ + (size_t)hh * DH_;

    for (int it = tid; it < 128 * 16; it += 256) {
        int r  = it >> 4;
        int c4 = (it & 15) * 4;
        float4 qv = *(const float4*)&Q[base + (size_t)(q0 + r) * D_ + c4];
        float* dst = &Qs[r * 65 + c4];
        dst[0] = qv.x * 0.125f; dst[1] = qv.y * 0.125f;
        dst[2] = qv.z * 0.125f; dst[3] = qv.w * 0.125f;
    }

    float m_run[8], l_run[8], oacc[8][4];
    #pragma unroll
    for (int i = 0; i < 8; i++) {
        m_run[i] = -1e30f; l_run[i] = 0.f;
        #pragma unroll
        for (int j = 0; j < 4; j++) oacc[i][j] = 0.f;
    }

    for (int t = 0; t < S_ / 64; t++) {
        int k0 = t * 64;
        for (int it = tid; it < 64 * 16; it += 256) {
            int r  = it >> 4;
            int c4 = (it & 15) * 4;
            float4 kv = *(const float4*)&K[base + (size_t)(k0 + r) * D_ + c4];
            float* dk = &Ks[r * 65 + c4];
            dk[0] = kv.x; dk[1] = kv.y; dk[2] = kv.z; dk[3] = kv.w;
            float4 vv = *(const float4*)&V[base + (size_t)(k0 + r) * D_ + c4];
            *(float4*)&Vs[r * 64 + c4] = vv;
        }
        __syncthreads();

        float sreg[8][4];
        #pragma unroll
        for (int i = 0; i < 8; i++)
            #pragma unroll
            for (int j = 0; j < 4; j++) sreg[i][j] = 0.f;

        #pragma unroll 8
        for (int k = 0; k < 64; k++) {
            float qv[8], kv[4];
            #pragma unroll
            for (int i = 0; i < 8; i++) qv[i] = Qs[(ty + 16 * i) * 65 + k];
            #pragma unroll
            for (int j = 0; j < 4; j++) kv[j] = Ks[(tx + 16 * j) * 65 + k];
            #pragma unroll
            for (int i = 0; i < 8; i++)
                #pragma unroll
                for (int j = 0; j < 4; j++)
                    sreg[i][j] += qv[i] * kv[j];
        }

        #pragma unroll
        for (int i = 0; i < 8; i++) {
            float mt = fmaxf(fmaxf(sreg[i][0], sreg[i][1]),
                             fmaxf(sreg[i][2], sreg[i][3]));
            #pragma unroll
            for (int o = 8; o > 0; o >>= 1)
                mt = fmaxf(mt, __shfl_xor_sync(0xffffffffu, mt, o));
            float mn   = fmaxf(m_run[i], mt);
            float corr = __expf(m_run[i] - mn);
            float ps = 0.f;
            #pragma unroll
            for (int j = 0; j < 4; j++) {
                float p = __expf(sreg[i][j] - mn);
                Ps[(ty + 16 * i) * 65 + tx + 16 * j] = p;
                ps += p;
            }
            #pragma unroll
            for (int o = 8; o > 0; o >>= 1)
                ps += __shfl_xor_sync(0xffffffffu, ps, o);
            l_run[i] = l_run[i] * corr + ps;
            m_run[i] = mn;
            #pragma unroll
            for (int j = 0; j < 4; j++) oacc[i][j] *= corr;
        }
        __syncthreads();

        #pragma unroll 8
        for (int c = 0; c < 64; c++) {
            float pv[8], vv[4];
            #pragma unroll
            for (int i = 0; i < 8; i++) pv[i] = Ps[(ty + 16 * i) * 65 + c];
            #pragma unroll
            for (int j = 0; j < 4; j++) vv[j] = Vs[c * 64 + tx + 16 * j];
            #pragma unroll
            for (int i = 0; i < 8; i++)
                #pragma unroll
                for (int j = 0; j < 4; j++)
                    oacc[i][j] += pv[i] * vv[j];
        }
        __syncthreads();
    }

    #pragma unroll
    for (int i = 0; i < 8; i++) {
        float inv = 1.0f / l_run[i];
        int r = q0 + ty + 16 * i;
        #pragma unroll
        for (int j = 0; j < 4; j++)
            O[base + (size_t)r * D_ + tx + 16 * j] = tf32r(oacc[i][j] * inv);
    }
}

// ---------------------------------------------------------------------------
// Launch
// ---------------------------------------------------------------------------
extern "C" void kernel_launch(void* const* d_in, const int* in_sizes, int n_in,
                              void* d_out, int out_size)
{
    (void)in_sizes; (void)n_in; (void)out_size;
    const float* x    = (const float*)d_in[0];
    const int*   lidx = (const int*)  d_in[1];
    const float* Wq = (const float*)d_in[2];  const float* bq = (const float*)d_in[3];
    const float* Wk = (const float*)d_in[4];  const float* bk = (const float*)d_in[5];
    const float* Wv = (const float*)d_in[6];  const float* bv = (const float*)d_in[7];
    const float* Wo = (const float*)d_in[8];  const float* bo = (const float*)d_in[9];
    const float* s1 = (const float*)d_in[10]; const float* b1n = (const float*)d_in[11];
    const float* s2 = (const float*)d_in[12]; const float* b2n = (const float*)d_in[13];
    const float* W1 = (const float*)d_in[14]; const float* bf1 = (const float*)d_in[15];
    const float* W2 = (const float*)d_in[16]; const float* bf2 = (const float*)d_in[17];
    float* out = (float*)d_out;

    float *h_, *q_, *k_, *v_, *at_, *ff_;
    float *wqT, *wkT, *wvT, *woT, *w1T, *w2T;
    cudaGetSymbolAddress((void**)&h_,  g_h);
    cudaGetSymbolAddress((void**)&q_,  g_q);
    cudaGetSymbolAddress((void**)&k_,  g_k);
    cudaGetSymbolAddress((void**)&v_,  g_v);
    cudaGetSymbolAddress((void**)&at_, g_attn);
    cudaGetSymbolAddress((void**)&ff_, g_ffn);
    cudaGetSymbolAddress((void**)&wqT, g_WqT);
    cudaGetSymbolAddress((void**)&wkT, g_WkT);
    cudaGetSymbolAddress((void**)&wvT, g_WvT);
    cudaGetSymbolAddress((void**)&woT, g_WoT);
    cudaGetSymbolAddress((void**)&w1T, g_W1T);
    cudaGetSymbolAddress((void**)&w2T, g_W2T);

    cudaFuncSetAttribute(attention_kernel,
                         cudaFuncAttributeMaxDynamicSharedMemorySize, AT_SMEM_BYTES);
    cudaFuncSetAttribute(gemm_mma<0,0,0>,
                         cudaFuncAttributeMaxDynamicSharedMemorySize, GEMM_SMEM);
    cudaFuncSetAttribute(gemm_mma<0,1,0>,
                         cudaFuncAttributeMaxDynamicSharedMemorySize, GEMM_SMEM);
    cudaFuncSetAttribute(gemm_mma<1,0,1>,
                         cudaFuncAttributeMaxDynamicSharedMemorySize, GEMM_SMEM);

    // Weight transpose + tf32 rounding
    dim3 tb(32, 8);
    transpose_round_kernel<<<dim3(D_/32, D_/32, L_), tb>>>(Wq, wqT, D_, D_);
    transpose_round_kernel<<<dim3(D_/32, D_/32, L_), tb>>>(Wk, wkT, D_, D_);
    transpose_round_kernel<<<dim3(D_/32, D_/32, L_), tb>>>(Wv, wvT, D_, D_);
    transpose_round_kernel<<<dim3(D_/32, D_/32, L_), tb>>>(Wo, woT, D_, D_);
    transpose_round_kernel<<<dim3(F_/32, D_/32, L_), tb>>>(W1, w1T, D_, F_);
    transpose_round_kernel<<<dim3(D_/32, F_/32, L_), tb>>>(W2, w2T, F_, D_);

    dim3 gD(D_ / 128, S_ / 128, B_);
    dim3 gF(F_ / 128, S_ / 128, B_);

    // LN1 -> h (tf32-rounded)
    ln_kernel<<<B_ * S_, 256>>>(x, s1, b1n, lidx, h_);
    // QKV (fp32 outputs for SIMT attention)
    gemm_mma<0,0,0><<<gD, 256, GEMM_SMEM>>>(h_, wqT, bq, lidx, nullptr, q_, S_, D_, D_);
    gemm_mma<0,0,0><<<gD, 256, GEMM_SMEM>>>(h_, wkT, bk, lidx, nullptr, k_, S_, D_, D_);
    gemm_mma<0,0,0><<<gD, 256, GEMM_SMEM>>>(h_, wvT, bv, lidx, nullptr, v_, S_, D_, D_);
    // Attention (tf32-rounded output -> Wo GEMM input)
    attention_kernel<<<dim3(S_ / 128, H_, B_), 256, AT_SMEM_BYTES>>>(q_, k_, v_, at_);
    // O-proj + residual(x) -> out
    gemm_mma<0,1,0><<<gD, 256, GEMM_SMEM>>>(at_, woT, bo, lidx, x, out, S_, D_, D_);
    // LN2 -> h (tf32-rounded)
    ln_kernel<<<B_ * S_, 256>>>(out, s2, b2n, lidx, h_);
    // FFN1 + GELU (tf32-rounded -> FFN2 input)
    gemm_mma<1,0,1><<<gF, 256, GEMM_SMEM>>>(h_, w1T, bf1, lidx, nullptr, ff_, S_, D_, F_);
    // FFN2 + residual(out) -> final
    gemm_mma<0,1,0><<<gD, 256, GEMM_SMEM>>>(ff_, w2T, bf2, lidx, out, out, S_, F_, D_);
}

// round 4
// speedup vs baseline: 1.9024x; 1.0017x over previous
#include <cuda_runtime.h>
#include <math.h>
#include <stdint.h>

// Problem dims
#define L_  8
#define B_  8
#define S_  2048
#define D_  1024
#define H_  16
#define DH_ 64
#define F_  4096

// ---------------------------------------------------------------------------
// Scratch (__device__ globals; allocation-guard-safe)
// ---------------------------------------------------------------------------
__device__ float g_h   [(size_t)B_ * S_ * D_];
__device__ float g_q   [(size_t)B_ * S_ * D_];
__device__ float g_k   [(size_t)B_ * S_ * D_];
__device__ float g_v   [(size_t)B_ * S_ * D_];
__device__ float g_attn[(size_t)B_ * S_ * D_];
__device__ float g_ffn [(size_t)B_ * S_ * F_];
// Transposed + tf32-rounded weights: Wt[l][n][k]
__device__ float g_WqT[(size_t)L_ * D_ * D_];
__device__ float g_WkT[(size_t)L_ * D_ * D_];
__device__ float g_WvT[(size_t)L_ * D_ * D_];
__device__ float g_WoT[(size_t)L_ * D_ * D_];
__device__ float g_W1T[(size_t)L_ * D_ * F_];
__device__ float g_W2T[(size_t)L_ * F_ * D_];

// ---------------------------------------------------------------------------
// Helpers (baseline PTX only — no 'a'-suffix accel features)
// ---------------------------------------------------------------------------
__device__ __forceinline__ uint32_t smem_u32(const void* p) {
    uint32_t a;
    asm("{ .reg .u64 t; cvta.to.shared.u64 t, %1; cvt.u32.u64 %0, t; }"
        : "=r"(a) : "l"(p));
    return a;
}

__device__ __forceinline__ float tf32r(float x) {   // round-to-nearest tf32
    uint32_t u;
    asm("cvt.rna.tf32.f32 %0, %1;" : "=r"(u) : "f"(x));
    return __uint_as_float(u);
}

#define SMEM_SWZ128(o) ((o) ^ (((o) >> 3) & 0x70))

#define CP_ASYNC16(dst_u32, src_ptr) \
    asm volatile("cp.async.cg.shared.global [%0], [%1], 16;" \
                 :: "r"(dst_u32), "l"(src_ptr))
#define CP_ASYNC_COMMIT() asm volatile("cp.async.commit_group;" ::: "memory")
#define CP_ASYNC_WAIT1()  asm volatile("cp.async.wait_group 1;" ::: "memory")
#define CP_ASYNC_WAIT0()  asm volatile("cp.async.wait_group 0;" ::: "memory")

__device__ __forceinline__ void ldsm_x4(uint32_t (&r)[4], uint32_t addr) {
    asm volatile("ldmatrix.sync.aligned.m8n8.x4.shared.b16 {%0,%1,%2,%3}, [%4];"
                 : "=r"(r[0]), "=r"(r[1]), "=r"(r[2]), "=r"(r[3]) : "r"(addr));
}

__device__ __forceinline__ void mma_tf32(float (&d)[4],
                                         const uint32_t (&a)[4],
                                         uint32_t b0, uint32_t b1) {
    asm volatile(
        "mma.sync.aligned.m16n8k8.row.col.f32.tf32.tf32.f32 "
        "{%0,%1,%2,%3}, {%4,%5,%6,%7}, {%8,%9}, {%0,%1,%2,%3};"
        : "+f"(d[0]), "+f"(d[1]), "+f"(d[2]), "+f"(d[3])
        : "r"(a[0]), "r"(a[1]), "r"(a[2]), "r"(a[3]), "r"(b0), "r"(b1));
}

// ---------------------------------------------------------------------------
// GELU (tanh approx — matches jax.nn.gelu default)
// ---------------------------------------------------------------------------
__device__ __forceinline__ float gelu_f(float x)
{
    float t = 0.7978845608028654f * (x + 0.044715f * x * x * x);
    float th;
    asm("tanh.approx.f32 %0, %1;" : "=f"(th) : "f"(t));
    return 0.5f * x * (1.0f + th);
}

// ---------------------------------------------------------------------------
// Weight transpose + tf32 RN round: W[l][K][N] -> Wt[l][N][K]
// ---------------------------------------------------------------------------
__global__ __launch_bounds__(256) void transpose_round_kernel(
    const float* __restrict__ W, float* __restrict__ Wt, int Kd, int Nd)
{
    __shared__ float t[32][33];
    int l  = blockIdx.z;
    int n0 = blockIdx.x * 32;
    int k0 = blockIdx.y * 32;
    const float* Wl  = W  + (size_t)l * Kd * Nd;
    float*       Wtl = Wt + (size_t)l * Nd * Kd;
    int c = threadIdx.x, r0 = threadIdx.y;
    #pragma unroll
    for (int i = 0; i < 4; i++) {
        int r = r0 + i * 8;
        t[r][c] = Wl[(size_t)(k0 + r) * Nd + n0 + c];
    }
    __syncthreads();
    #pragma unroll
    for (int i = 0; i < 4; i++) {
        int r = r0 + i * 8;
        Wtl[(size_t)(n0 + r) * Kd + k0 + c] = tf32r(t[c][r]);
    }
}

// ---------------------------------------------------------------------------
// LayerNorm (rounds output to tf32 — feeds tensor-core GEMMs)
// ---------------------------------------------------------------------------
__global__ __launch_bounds__(256) void ln_kernel(
    const float* __restrict__ X,
    const float* __restrict__ sall, const float* __restrict__ ball,
    const int* __restrict__ lidx, float* __restrict__ Y)
{
    int row = blockIdx.x;
    int b   = row / S_;
    int tid = threadIdx.x;

    float4 xv = ((const float4*)(X + (size_t)row * D_))[tid];
    float s  = xv.x + xv.y + xv.z + xv.w;
    float ss = xv.x*xv.x + xv.y*xv.y + xv.z*xv.z + xv.w*xv.w;
    #pragma unroll
    for (int o = 16; o > 0; o >>= 1) {
        s  += __shfl_xor_sync(0xffffffffu, s,  o);
        ss += __shfl_xor_sync(0xffffffffu, ss, o);
    }
    __shared__ float rs[8], rss[8], mv[2];
    int wid = tid >> 5, lane = tid & 31;
    if (lane == 0) { rs[wid] = s; rss[wid] = ss; }
    __syncthreads();
    if (tid == 0) {
        float a = 0.f, c = 0.f;
        #pragma unroll
        for (int w = 0; w < 8; w++) { a += rs[w]; c += rss[w]; }
        float mean = a * (1.0f / D_);
        float var  = c * (1.0f / D_) - mean * mean;
        mv[0] = mean; mv[1] = rsqrtf(var + 1e-5f);
    }
    __syncthreads();
    float mean = mv[0], rstd = mv[1];

    int li = lidx[b];
    float4 sv = ((const float4*)(sall + (size_t)li * D_))[tid];
    float4 bv = ((const float4*)(ball + (size_t)li * D_))[tid];
    float4 o;
    o.x = tf32r((xv.x - mean) * rstd * sv.x + bv.x);
    o.y = tf32r((xv.y - mean) * rstd * sv.y + bv.y);
    o.z = tf32r((xv.z - mean) * rstd * sv.z + bv.z);
    o.w = tf32r((xv.w - mean) * rstd * sv.w + bv.w);
    ((float4*)(Y + (size_t)row * D_))[tid] = o;
}

// ---------------------------------------------------------------------------
// mma.sync tf32 GEMM: C[b] = A[b](MxK) @ Wt[lidx[b]](NxK)^T + bias
//                     (+GELU) (+residual) (+tf32 round on store)
// 128x128 tile, BK=32, 8 warps (2x4), warp tile 64x32 of m16n8k8.
// 3-stage cp.async ring, SW128 swizzle, ldmatrix fragment loads.
// ---------------------------------------------------------------------------
#define GEMM_SMEM (1024 + 3 * 32768)

template <int ACT, int RES, int RND>
__global__ __launch_bounds__(256, 2)
void gemm_mma(const float* __restrict__ A, const float* __restrict__ WT,
              const float* __restrict__ biasall, const int* __restrict__ lidx,
              const float* __restrict__ Res, float* __restrict__ C,
              int M, int K, int N)
{
    extern __shared__ __align__(16) char smraw[];
    uint32_t sbase = (smem_u32(smraw) + 1023u) & ~1023u;

    int tid  = threadIdx.x;
    int wid  = tid >> 5;
    int lane = tid & 31;
    int wm   = wid >> 2;      // 0..1
    int wn   = wid & 3;       // 0..3
    int b    = blockIdx.z;
    int li   = lidx[b];
    int row0 = blockIdx.y * 128;
    int col0 = blockIdx.x * 128;

    const float* Ag = A  + (size_t)b  * M * K + (size_t)row0 * K;
    const float* Bg = WT + (size_t)li * N * K + (size_t)col0 * K;

    float acc[4][4][4];
    #pragma unroll
    for (int i = 0; i < 4; i++)
        #pragma unroll
        for (int j = 0; j < 4; j++)
            #pragma unroll
            for (int q = 0; q < 4; q++) acc[i][j][q] = 0.f;

    // Per-thread cp.async slots: A and B tiles are each 128 rows x 128B.
    int lrow = tid >> 1;              // 0..127
    int lkb  = (tid & 1) * 64;        // 0 or 64 bytes; 2 chunks of 16B each... 
    // Simpler: 1024 16B-chunks per tile, 4 per thread.
    auto load_stage = [&](int kc, int stg) {
        uint32_t sA = sbase + (uint32_t)stg * 32768u;
        uint32_t sB = sA + 16384u;
        const float* Ak = Ag + kc * 32;
        const float* Bk = Bg + kc * 32;
        #pragma unroll
        for (int p = 0; p < 4; p++) {
            int idx = tid + p * 256;
            int r  = idx >> 3;
            int kb = (idx & 7) * 16;            // byte offset in row
            uint32_t sw = SMEM_SWZ128((uint32_t)(r * 128 + kb));
            CP_ASYNC16(sA + sw, Ak + (size_t)r * K + (kb >> 2));
            CP_ASYNC16(sB + sw, Bk + (size_t)r * K + (kb >> 2));
        }
        CP_ASYNC_COMMIT();
    };

    int nk = K >> 5;
    load_stage(0, 0);
    load_stage(1, 1);

    int lr = lane & 15;      // row-within-16 for ldmatrix addressing
    int lh = (lane >> 4) * 16;  // +16B for second k-half

    for (int i = 0; i < nk; i++) {
        if (i < nk - 2) CP_ASYNC_WAIT1(); else CP_ASYNC_WAIT0();
        __syncthreads();
        if (i + 2 < nk) load_stage(i + 2, (i + 2) % 3);

        uint32_t sA = sbase + (uint32_t)(i % 3) * 32768u;
        uint32_t sB = sA + 16384u;

        #pragma unroll
        for (int ks = 0; ks < 4; ks++) {
            uint32_t afr[4][4];
            uint32_t bfr[2][4];
            #pragma unroll
            for (int mf = 0; mf < 4; mf++) {
                uint32_t off = (uint32_t)((64 * wm + 16 * mf + lr) * 128
                                          + ks * 32 + lh);
                ldsm_x4(afr[mf], sA + SMEM_SWZ128(off));
            }
            #pragma unroll
            for (int bf = 0; bf < 2; bf++) {
                uint32_t off = (uint32_t)((32 * wn + 16 * bf + lr) * 128
                                          + ks * 32 + lh);
                ldsm_x4(bfr[bf], sB + SMEM_SWZ128(off));
            }
            // bfr[bf]: r0=b0(nf=2bf), r1=b0(nf=2bf+1), r2=b1(nf=2bf), r3=b1(nf=2bf+1)
            #pragma unroll
            for (int mf = 0; mf < 4; mf++)
                #pragma unroll
                for (int nf = 0; nf < 4; nf++)
                    mma_tf32(acc[mf][nf], afr[mf],
                             bfr[nf >> 1][nf & 1], bfr[nf >> 1][2 + (nf & 1)]);
        }
    }
    (void)lrow; (void)lkb;

    // Epilogue: c0,c1 at (row=qr, col=qc..qc+1), c2,c3 at row+8.
    int qr = lane >> 2;
    int qc = (lane & 3) * 2;
    const float* bp = biasall + (size_t)li * N;
    #pragma unroll
    for (int mf = 0; mf < 4; mf++) {
        int r = row0 + 64 * wm + 16 * mf + qr;
        #pragma unroll
        for (int nf = 0; nf < 4; nf++) {
            int cc = col0 + 32 * wn + 8 * nf + qc;
            #pragma unroll
            for (int half = 0; half < 2; half++) {
                int rr = r + half * 8;
                float v0 = acc[mf][nf][half * 2 + 0] + bp[cc + 0];
                float v1 = acc[mf][nf][half * 2 + 1] + bp[cc + 1];
                if (ACT) { v0 = gelu_f(v0); v1 = gelu_f(v1); }
                if (RES) {
                    const float* rp = Res + (size_t)b * M * N + (size_t)rr * N + cc;
                    v0 += rp[0]; v1 += rp[1];
                }
                if (RND) { v0 = tf32r(v0); v1 = tf32r(v1); }
                float2 o2 = make_float2(v0, v1);
                *(float2*)&C[(size_t)b * M * N + (size_t)rr * N + cc] = o2;
            }
        }
    }
}

// ---------------------------------------------------------------------------
// Flash attention (fp32 SIMT — unchanged from the passing R1 version,
// plus tf32-rounded output store since it feeds the Wo GEMM)
// ---------------------------------------------------------------------------
#define AT_SMEM_FLOATS (128*65 + 64*65 + 64*64 + 128*65)
#define AT_SMEM_BYTES  (AT_SMEM_FLOATS * 4)

__global__ __launch_bounds__(256) void attention_kernel(
    const float* __restrict__ Q, const float* __restrict__ K,
    const float* __restrict__ V, float* __restrict__ O)
{
    extern __shared__ float sm[];
    float* Qs = sm;
    float* Ks = Qs + 128 * 65;
    float* Vs = Ks + 64 * 65;
    float* Ps = Vs + 64 * 64;

    int q0 = blockIdx.x * 128;
    int hh = blockIdx.y;
    int b  = blockIdx.z;
    int tid = threadIdx.x;
    int tx  = tid & 15;
    int ty  = tid >> 4;

    size_t base = (size_t)b * S_ * D_ + (size_t)hh * DH_;

    for (int it = tid; it < 128 * 16; it += 256) {
        int r  = it >> 4;
        int c4 = (it & 15) * 4;
        float4 qv = *(const float4*)&Q[base + (size_t)(q0 + r) * D_ + c4];
        float* dst = &Qs[r * 65 + c4];
        dst[0] = qv.x * 0.125f; dst[1] = qv.y * 0.125f;
        dst[2] = qv.z * 0.125f; dst[3] = qv.w * 0.125f;
    }

    float m_run[8], l_run[8], oacc[8][4];
    #pragma unroll
    for (int i = 0; i < 8; i++) {
        m_run[i] = -1e30f; l_run[i] = 0.f;
        #pragma unroll
        for (int j = 0; j < 4; j++) oacc[i][j] = 0.f;
    }

    for (int t = 0; t < S_ / 64; t++) {
        int k0 = t * 64;
        for (int it = tid; it < 64 * 16; it += 256) {
            int r  = it >> 4;
            int c4 = (it & 15) * 4;
            float4 kv = *(const float4*)&K[base + (size_t)(k0 + r) * D_ + c4];
            float* dk = &Ks[r * 65 + c4];
            dk[0] = kv.x; dk[1] = kv.y; dk[2] = kv.z; dk[3] = kv.w;
            float4 vv = *(const float4*)&V[base + (size_t)(k0 + r) * D_ + c4];
            *(float4*)&Vs[r * 64 + c4] = vv;
        }
        __syncthreads();

        float sreg[8][4];
        #pragma unroll
        for (int i = 0; i < 8; i++)
            #pragma unroll
            for (int j = 0; j < 4; j++) sreg[i][j] = 0.f;

        #pragma unroll 8
        for (int k = 0; k < 64; k++) {
            float qv[8], kv[4];
            #pragma unroll
            for (int i = 0; i < 8; i++) qv[i] = Qs[(ty + 16 * i) * 65 + k];
            #pragma unroll
            for (int j = 0; j < 4; j++) kv[j] = Ks[(tx + 16 * j) * 65 + k];
            #pragma unroll
            for (int i = 0; i < 8; i++)
                #pragma unroll
                for (int j = 0; j < 4; j++)
                    sreg[i][j] += qv[i] * kv[j];
        }

        #pragma unroll
        for (int i = 0; i < 8; i++) {
            float mt = fmaxf(fmaxf(sreg[i][0], sreg[i][1]),
                             fmaxf(sreg[i][2], sreg[i][3]));
            #pragma unroll
            for (int o = 8; o > 0; o >>= 1)
                mt = fmaxf(mt, __shfl_xor_sync(0xffffffffu, mt, o));
            float mn   = fmaxf(m_run[i], mt);
            float corr = __expf(m_run[i] - mn);
            float ps = 0.f;
            #pragma unroll
            for (int j = 0; j < 4; j++) {
                float p = __expf(sreg[i][j] - mn);
                Ps[(ty + 16 * i) * 65 + tx + 16 * j] = p;
                ps += p;
            }
            #pragma unroll
            for (int o = 8; o > 0; o >>= 1)
                ps += __shfl_xor_sync(0xffffffffu, ps, o);
            l_run[i] = l_run[i] * corr + ps;
            m_run[i] = mn;
            #pragma unroll
            for (int j = 0; j < 4; j++) oacc[i][j] *= corr;
        }
        __syncthreads();

        #pragma unroll 8
        for (int c = 0; c < 64; c++) {
            float pv[8], vv[4];
            #pragma unroll
            for (int i = 0; i < 8; i++) pv[i] = Ps[(ty + 16 * i) * 65 + c];
            #pragma unroll
            for (int j = 0; j < 4; j++) vv[j] = Vs[c * 64 + tx + 16 * j];
            #pragma unroll
            for (int i = 0; i < 8; i++)
                #pragma unroll
                for (int j = 0; j < 4; j++)
                    oacc[i][j] += pv[i] * vv[j];
        }
        __syncthreads();
    }

    #pragma unroll
    for (int i = 0; i < 8; i++) {
        float inv = 1.0f / l_run[i];
        int r = q0 + ty + 16 * i;
        #pragma unroll
        for (int j = 0; j < 4; j++)
            O[base + (size_t)r * D_ + tx + 16 * j] = tf32r(oacc[i][j] * inv);
    }
}

// ---------------------------------------------------------------------------
// Launch
// ---------------------------------------------------------------------------
extern "C" void kernel_launch(void* const* d_in, const int* in_sizes, int n_in,
                              void* d_out, int out_size)
{
    (void)in_sizes; (void)n_in; (void)out_size;
    const float* x    = (const float*)d_in[0];
    const int*   lidx = (const int*)  d_in[1];
    const float* Wq = (const float*)d_in[2];  const float* bq = (const float*)d_in[3];
    const float* Wk = (const float*)d_in[4];  const float* bk = (const float*)d_in[5];
    const float* Wv = (const float*)d_in[6];  const float* bv = (const float*)d_in[7];
    const float* Wo = (const float*)d_in[8];  const float* bo = (const float*)d_in[9];
    const float* s1 = (const float*)d_in[10]; const float* b1n = (const float*)d_in[11];
    const float* s2 = (const float*)d_in[12]; const float* b2n = (const float*)d_in[13];
    const float* W1 = (const float*)d_in[14]; const float* bf1 = (const float*)d_in[15];
    const float* W2 = (const float*)d_in[16]; const float* bf2 = (const float*)d_in[17];
    float* out = (float*)d_out;

    float *h_, *q_, *k_, *v_, *at_, *ff_;
    float *wqT, *wkT, *wvT, *woT, *w1T, *w2T;
    cudaGetSymbolAddress((void**)&h_,  g_h);
    cudaGetSymbolAddress((void**)&q_,  g_q);
    cudaGetSymbolAddress((void**)&k_,  g_k);
    cudaGetSymbolAddress((void**)&v_,  g_v);
    cudaGetSymbolAddress((void**)&at_, g_attn);
    cudaGetSymbolAddress((void**)&ff_, g_ffn);
    cudaGetSymbolAddress((void**)&wqT, g_WqT);
    cudaGetSymbolAddress((void**)&wkT, g_WkT);
    cudaGetSymbolAddress((void**)&wvT, g_WvT);
    cudaGetSymbolAddress((void**)&woT, g_WoT);
    cudaGetSymbolAddress((void**)&w1T, g_W1T);
    cudaGetSymbolAddress((void**)&w2T, g_W2T);

    cudaFuncSetAttribute(attention_kernel,
                         cudaFuncAttributeMaxDynamicSharedMemorySize, AT_SMEM_BYTES);
    cudaFuncSetAttribute(gemm_mma<0,0,0>,
                         cudaFuncAttributeMaxDynamicSharedMemorySize, GEMM_SMEM);
    cudaFuncSetAttribute(gemm_mma<0,1,0>,
                         cudaFuncAttributeMaxDynamicSharedMemorySize, GEMM_SMEM);
    cudaFuncSetAttribute(gemm_mma<1,0,1>,
                         cudaFuncAttributeMaxDynamicSharedMemorySize, GEMM_SMEM);

    // Weight transpose + tf32 rounding
    dim3 tb(32, 8);
    transpose_round_kernel<<<dim3(D_/32, D_/32, L_), tb>>>(Wq, wqT, D_, D_);
    transpose_round_kernel<<<dim3(D_/32, D_/32, L_), tb>>>(Wk, wkT, D_, D_);
    transpose_round_kernel<<<dim3(D_/32, D_/32, L_), tb>>>(Wv, wvT, D_, D_);
    transpose_round_kernel<<<dim3(D_/32, D_/32, L_), tb>>>(Wo, woT, D_, D_);
    transpose_round_kernel<<<dim3(F_/32, D_/32, L_), tb>>>(W1, w1T, D_, F_);
    transpose_round_kernel<<<dim3(D_/32, F_/32, L_), tb>>>(W2, w2T, F_, D_);

    dim3 gD(D_ / 128, S_ / 128, B_);
    dim3 gF(F_ / 128, S_ / 128, B_);

    // LN1 -> h (tf32-rounded)
    ln_kernel<<<B_ * S_, 256>>>(x, s1, b1n, lidx, h_);
    // QKV (fp32 outputs for SIMT attention)
    gemm_mma<0,0,0><<<gD, 256, GEMM_SMEM>>>(h_, wqT, bq, lidx, nullptr, q_, S_, D_, D_);
    gemm_mma<0,0,0><<<gD, 256, GEMM_SMEM>>>(h_, wkT, bk, lidx, nullptr, k_, S_, D_, D_);
    gemm_mma<0,0,0><<<gD, 256, GEMM_SMEM>>>(h_, wvT, bv, lidx, nullptr, v_, S_, D_, D_);
    // Attention (tf32-rounded output -> Wo GEMM input)
    attention_kernel<<<dim3(S_ / 128, H_, B_), 256, AT_SMEM_BYTES>>>(q_, k_, v_, at_);
    // O-proj + residual(x) -> out
    gemm_mma<0,1,0><<<gD, 256, GEMM_SMEM>>>(at_, woT, bo, lidx, x, out, S_, D_, D_);
    // LN2 -> h (tf32-rounded)
    ln_kernel<<<B_ * S_, 256>>>(out, s2, b2n, lidx, h_);
    // FFN1 + GELU (tf32-rounded -> FFN2 input)
    gemm_mma<1,0,1><<<gF, 256, GEMM_SMEM>>>(h_, w1T, bf1, lidx, nullptr, ff_, S_, D_, F_);
    // FFN2 + residual(out) -> final
    gemm_mma<0,1,0><<<gD, 256, GEMM_SMEM>>>(ff_, w2T, bf2, lidx, out, out, S_, F_, D_);
}

// round 5
// speedup vs baseline: 1.9033x; 1.0005x over previous
#include <cuda_runtime.h>
#include <math.h>
#include <stdint.h>

// Problem dims
#define L_  8
#define B_  8
#define S_  2048
#define D_  1024
#define H_  16
#define DH_ 64
#define F_  4096

// ---------------------------------------------------------------------------
// Scratch (__device__ globals; allocation-guard-safe)
// ---------------------------------------------------------------------------
__device__ float g_h   [(size_t)B_ * S_ * D_];
__device__ float g_q   [(size_t)B_ * S_ * D_];
__device__ float g_k   [(size_t)B_ * S_ * D_];
__device__ float g_v   [(size_t)B_ * S_ * D_];
__device__ float g_attn[(size_t)B_ * S_ * D_];
__device__ float g_ffn [(size_t)B_ * S_ * F_];
// Transposed + tf32-rounded weights: Wt[l][n][k]
__device__ float g_WqT[(size_t)L_ * D_ * D_];
__device__ float g_WkT[(size_t)L_ * D_ * D_];
__device__ float g_WvT[(size_t)L_ * D_ * D_];
__device__ float g_WoT[(size_t)L_ * D_ * D_];
__device__ float g_W1T[(size_t)L_ * D_ * F_];
__device__ float g_W2T[(size_t)L_ * F_ * D_];

// ---------------------------------------------------------------------------
// Helpers (baseline PTX only — no 'a'-suffix accel features)
// ---------------------------------------------------------------------------
__device__ __forceinline__ uint32_t smem_u32(const void* p) {
    uint32_t a;
    asm("{ .reg .u64 t; cvta.to.shared.u64 t, %1; cvt.u32.u64 %0, t; }"
        : "=r"(a) : "l"(p));
    return a;
}

__device__ __forceinline__ float tf32r(float x) {   // round-to-nearest tf32
    uint32_t u;
    asm("cvt.rna.tf32.f32 %0, %1;" : "=r"(u) : "f"(x));
    return __uint_as_float(u);
}

#define SMEM_SWZ128(o) ((o) ^ (((o) >> 3) & 0x70))

#define CP_ASYNC16(dst_u32, src_ptr) \
    asm volatile("cp.async.cg.shared.global [%0], [%1], 16;" \
                 :: "r"(dst_u32), "l"(src_ptr))
#define CP_ASYNC_COMMIT() asm volatile("cp.async.commit_group;" ::: "memory")
#define CP_ASYNC_WAIT1()  asm volatile("cp.async.wait_group 1;" ::: "memory")
#define CP_ASYNC_WAIT0()  asm volatile("cp.async.wait_group 0;" ::: "memory")

__device__ __forceinline__ void ldsm_x4(uint32_t (&r)[4], uint32_t addr) {
    asm volatile("ldmatrix.sync.aligned.m8n8.x4.shared.b16 {%0,%1,%2,%3}, [%4];"
                 : "=r"(r[0]), "=r"(r[1]), "=r"(r[2]), "=r"(r[3]) : "r"(addr));
}

__device__ __forceinline__ void mma_tf32(float (&d)[4],
                                         const uint32_t (&a)[4],
                                         uint32_t b0, uint32_t b1) {
    asm volatile(
        "mma.sync.aligned.m16n8k8.row.col.f32.tf32.tf32.f32 "
        "{%0,%1,%2,%3}, {%4,%5,%6,%7}, {%8,%9}, {%0,%1,%2,%3};"
        : "+f"(d[0]), "+f"(d[1]), "+f"(d[2]), "+f"(d[3])
        : "r"(a[0]), "r"(a[1]), "r"(a[2]), "r"(a[3]), "r"(b0), "r"(b1));
}

// ---------------------------------------------------------------------------
// GELU (tanh approx — matches jax.nn.gelu default)
// ---------------------------------------------------------------------------
__device__ __forceinline__ float gelu_f(float x)
{
    float t = 0.7978845608028654f * (x + 0.044715f * x * x * x);
    float th;
    asm("tanh.approx.f32 %0, %1;" : "=f"(th) : "f"(t));
    return 0.5f * x * (1.0f + th);
}

// ---------------------------------------------------------------------------
// Weight transpose + tf32 RN round: W[l][K][N] -> Wt[l][N][K]
// ---------------------------------------------------------------------------
__global__ __launch_bounds__(256) void transpose_round_kernel(
    const float* __restrict__ W, float* __restrict__ Wt, int Kd, int Nd)
{
    __shared__ float t[32][33];
    int l  = blockIdx.z;
    int n0 = blockIdx.x * 32;
    int k0 = blockIdx.y * 32;
    const float* Wl  = W  + (size_t)l * Kd * Nd;
    float*       Wtl = Wt + (size_t)l * Nd * Kd;
    int c = threadIdx.x, r0 = threadIdx.y;
    #pragma unroll
    for (int i = 0; i < 4; i++) {
        int r = r0 + i * 8;
        t[r][c] = Wl[(size_t)(k0 + r) * Nd + n0 + c];
    }
    __syncthreads();
    #pragma unroll
    for (int i = 0; i < 4; i++) {
        int r = r0 + i * 8;
        Wtl[(size_t)(n0 + r) * Kd + k0 + c] = tf32r(t[c][r]);
    }
}

// ---------------------------------------------------------------------------
// LayerNorm (rounds output to tf32 — feeds tensor-core GEMMs)
// ---------------------------------------------------------------------------
__global__ __launch_bounds__(256) void ln_kernel(
    const float* __restrict__ X,
    const float* __restrict__ sall, const float* __restrict__ ball,
    const int* __restrict__ lidx, float* __restrict__ Y)
{
    int row = blockIdx.x;
    int b   = row / S_;
    int tid = threadIdx.x;

    float4 xv = ((const float4*)(X + (size_t)row * D_))[tid];
    float s  = xv.x + xv.y + xv.z + xv.w;
    float ss = xv.x*xv.x + xv.y*xv.y + xv.z*xv.z + xv.w*xv.w;
    #pragma unroll
    for (int o = 16; o > 0; o >>= 1) {
        s  += __shfl_xor_sync(0xffffffffu, s,  o);
        ss += __shfl_xor_sync(0xffffffffu, ss, o);
    }
    __shared__ float rs[8], rss[8], mv[2];
    int wid = tid >> 5, lane = tid & 31;
    if (lane == 0) { rs[wid] = s; rss[wid] = ss; }
    __syncthreads();
    if (tid == 0) {
        float a = 0.f, c = 0.f;
        #pragma unroll
        for (int w = 0; w < 8; w++) { a += rs[w]; c += rss[w]; }
        float mean = a * (1.0f / D_);
        float var  = c * (1.0f / D_) - mean * mean;
        mv[0] = mean; mv[1] = rsqrtf(var + 1e-5f);
    }
    __syncthreads();
    float mean = mv[0], rstd = mv[1];

    int li = lidx[b];
    float4 sv = ((const float4*)(sall + (size_t)li * D_))[tid];
    float4 bv = ((const float4*)(ball + (size_t)li * D_))[tid];
    float4 o;
    o.x = tf32r((xv.x - mean) * rstd * sv.x + bv.x);
    o.y = tf32r((xv.y - mean) * rstd * sv.y + bv.y);
    o.z = tf32r((xv.z - mean) * rstd * sv.z + bv.z);
    o.w = tf32r((xv.w - mean) * rstd * sv.w + bv.w);
    ((float4*)(Y + (size_t)row * D_))[tid] = o;
}

// ---------------------------------------------------------------------------
// mma.sync tf32 GEMM: C[b] = A[b](MxK) @ Wt[lidx[b]](NxK)^T + bias
//                     (+GELU) (+residual) (+tf32 round on store)
// 128x128 tile, BK=32, 8 warps (2x4), warp tile 64x32 of m16n8k8.
// 3-stage cp.async ring, SW128 swizzle, ldmatrix fragment loads.
// ---------------------------------------------------------------------------
#define GEMM_SMEM (1024 + 3 * 32768)

template <int ACT, int RES, int RND>
__global__ __launch_bounds__(256, 2)
void gemm_mma(const float* __restrict__ A, const float* __restrict__ WT,
              const float* __restrict__ biasall, const int* __restrict__ lidx,
              const float* __restrict__ Res, float* __restrict__ C,
              int M, int K, int N)
{
    extern __shared__ __align__(16) char smraw[];
    uint32_t sbase = (smem_u32(smraw) + 1023u) & ~1023u;

    int tid  = threadIdx.x;
    int wid  = tid >> 5;
    int lane = tid & 31;
    int wm   = wid >> 2;      // 0..1
    int wn   = wid & 3;       // 0..3
    int b    = blockIdx.z;
    int li   = lidx[b];
    int row0 = blockIdx.y * 128;
    int col0 = blockIdx.x * 128;

    const float* Ag = A  + (size_t)b  * M * K + (size_t)row0 * K;
    const float* Bg = WT + (size_t)li * N * K + (size_t)col0 * K;

    float acc[4][4][4];
    #pragma unroll
    for (int i = 0; i < 4; i++)
        #pragma unroll
        for (int j = 0; j < 4; j++)
            #pragma unroll
            for (int q = 0; q < 4; q++) acc[i][j][q] = 0.f;

    // Per-thread cp.async slots: A and B tiles are each 128 rows x 128B.
    int lrow = tid >> 1;              // 0..127
    int lkb  = (tid & 1) * 64;        // 0 or 64 bytes; 2 chunks of 16B each... 
    // Simpler: 1024 16B-chunks per tile, 4 per thread.
    auto load_stage = [&](int kc, int stg) {
        uint32_t sA = sbase + (uint32_t)stg * 32768u;
        uint32_t sB = sA + 16384u;
        const float* Ak = Ag + kc * 32;
        const float* Bk = Bg + kc * 32;
        #pragma unroll
        for (int p = 0; p < 4; p++) {
            int idx = tid + p * 256;
            int r  = idx >> 3;
            int kb = (idx & 7) * 16;            // byte offset in row
            uint32_t sw = SMEM_SWZ128((uint32_t)(r * 128 + kb));
            CP_ASYNC16(sA + sw, Ak + (size_t)r * K + (kb >> 2));
            CP_ASYNC16(sB + sw, Bk + (size_t)r * K + (kb >> 2));
        }
        CP_ASYNC_COMMIT();
    };

    int nk = K >> 5;
    load_stage(0, 0);
    load_stage(1, 1);

    int lr = lane & 15;      // row-within-16 for ldmatrix addressing
    int lh = (lane >> 4) * 16;  // +16B for second k-half

    for (int i = 0; i < nk; i++) {
        if (i < nk - 2) CP_ASYNC_WAIT1(); else CP_ASYNC_WAIT0();
        __syncthreads();
        if (i + 2 < nk) load_stage(i + 2, (i + 2) % 3);

        uint32_t sA = sbase + (uint32_t)(i % 3) * 32768u;
        uint32_t sB = sA + 16384u;

        #pragma unroll
        for (int ks = 0; ks < 4; ks++) {
            uint32_t afr[4][4];
            uint32_t bfr[2][4];
            #pragma unroll
            for (int mf = 0; mf < 4; mf++) {
                uint32_t off = (uint32_t)((64 * wm + 16 * mf + lr) * 128
                                          + ks * 32 + lh);
                ldsm_x4(afr[mf], sA + SMEM_SWZ128(off));
            }
            #pragma unroll
            for (int bf = 0; bf < 2; bf++) {
                uint32_t off = (uint32_t)((32 * wn + 16 * bf + lr) * 128
                                          + ks * 32 + lh);
                ldsm_x4(bfr[bf], sB + SMEM_SWZ128(off));
            }
            // bfr[bf]: r0=b0(nf=2bf), r1=b0(nf=2bf+1), r2=b1(nf=2bf), r3=b1(nf=2bf+1)
            #pragma unroll
            for (int mf = 0; mf < 4; mf++)
                #pragma unroll
                for (int nf = 0; nf < 4; nf++)
                    mma_tf32(acc[mf][nf], afr[mf],
                             bfr[nf >> 1][nf & 1], bfr[nf >> 1][2 + (nf & 1)]);
        }
    }
    (void)lrow; (void)lkb;

    // Epilogue: c0,c1 at (row=qr, col=qc..qc+1), c2,c3 at row+8.
    int qr = lane >> 2;
    int qc = (lane & 3) * 2;
    const float* bp = biasall + (size_t)li * N;
    #pragma unroll
    for (int mf = 0; mf < 4; mf++) {
        int r = row0 + 64 * wm + 16 * mf + qr;
        #pragma unroll
        for (int nf = 0; nf < 4; nf++) {
            int cc = col0 + 32 * wn + 8 * nf + qc;
            #pragma unroll
            for (int half = 0; half < 2; half++) {
                int rr = r + half * 8;
                float v0 = acc[mf][nf][half * 2 + 0] + bp[cc + 0];
                float v1 = acc[mf][nf][half * 2 + 1] + bp[cc + 1];
                if (ACT) { v0 = gelu_f(v0); v1 = gelu_f(v1); }
                if (RES) {
                    const float* rp = Res + (size_t)b * M * N + (size_t)rr * N + cc;
                    v0 += rp[0]; v1 += rp[1];
                }
                if (RND) { v0 = tf32r(v0); v1 = tf32r(v1); }
                float2 o2 = make_float2(v0, v1);
                *(float2*)&C[(size_t)b * M * N + (size_t)rr * N + cc] = o2;
            }
        }
    }
}

// ---------------------------------------------------------------------------
// Flash attention (fp32 SIMT — unchanged from the passing R1 version,
// plus tf32-rounded output store since it feeds the Wo GEMM)
// ---------------------------------------------------------------------------
#define AT_SMEM_FLOATS (128*65 + 64*65 + 64*64 + 128*65)
#define AT_SMEM_BYTES  (AT_SMEM_FLOATS * 4)

__global__ __launch_bounds__(256) void attention_kernel(
    const float* __restrict__ Q, const float* __restrict__ K,
    const float* __restrict__ V, float* __restrict__ O)
{
    extern __shared__ float sm[];
    float* Qs = sm;
    float* Ks = Qs + 128 * 65;
    float* Vs = Ks + 64 * 65;
    float* Ps = Vs + 64 * 64;

    int q0 = blockIdx.x * 128;
    int hh = blockIdx.y;
    int b  = blockIdx.z;
    int tid = threadIdx.x;
    int tx  = tid & 15;
    int ty  = tid >> 4;

    size_t base = (size_t)b * S_ * D_ + (size_t)hh * DH_;

    for (int it = tid; it < 128 * 16; it += 256) {
        int r  = it >> 4;
        int c4 = (it & 15) * 4;
        float4 qv = *(const float4*)&Q[base + (size_t)(q0 + r) * D_ + c4];
        float* dst = &Qs[r * 65 + c4];
        dst[0] = qv.x * 0.125f; dst[1] = qv.y * 0.125f;
        dst[2] = qv.z * 0.125f; dst[3] = qv.w * 0.125f;
    }

    float m_run[8], l_run[8], oacc[8][4];
    #pragma unroll
    for (int i = 0; i < 8; i++) {
        m_run[i] = -1e30f; l_run[i] = 0.f;
        #pragma unroll
        for (int j = 0; j < 4; j++) oacc[i][j] = 0.f;
    }

    for (int t = 0; t < S_ / 64; t++) {
        int k0 = t * 64;
        for (int it = tid; it < 64 * 16; it += 256) {
            int r  = it >> 4;
            int c4 = (it & 15) * 4;
            float4 kv = *(const float4*)&K[base + (size_t)(k0 + r) * D_ + c4];
            float* dk = &Ks[r * 65 + c4];
            dk[0] = kv.x; dk[1] = kv.y; dk[2] = kv.z; dk[3] = kv.w;
            float4 vv = *(const float4*)&V[base + (size_t)(k0 + r) * D_ + c4];
            *(float4*)&Vs[r * 64 + c4] = vv;
        }
        __syncthreads();

        float sreg[8][4];
        #pragma unroll
        for (int i = 0; i < 8; i++)
            #pragma unroll
            for (int j = 0; j < 4; j++) sreg[i][j] = 0.f;

        #pragma unroll 8
        for (int k = 0; k < 64; k++) {
            float qv[8], kv[4];
            #pragma unroll
            for (int i = 0; i < 8; i++) qv[i] = Qs[(ty + 16 * i) * 65 + k];
            #pragma unroll
            for (int j = 0; j < 4; j++) kv[j] = Ks[(tx + 16 * j) * 65 + k];
            #pragma unroll
            for (int i = 0; i < 8; i++)
                #pragma unroll
                for (int j = 0; j < 4; j++)
                    sreg[i][j] += qv[i] * kv[j];
        }

        #pragma unroll
        for (int i = 0; i < 8; i++) {
            float mt = fmaxf(fmaxf(sreg[i][0], sreg[i][1]),
                             fmaxf(sreg[i][2], sreg[i][3]));
            #pragma unroll
            for (int o = 8; o > 0; o >>= 1)
                mt = fmaxf(mt, __shfl_xor_sync(0xffffffffu, mt, o));
            float mn   = fmaxf(m_run[i], mt);
            float corr = __expf(m_run[i] - mn);
            float ps = 0.f;
            #pragma unroll
            for (int j = 0; j < 4; j++) {
                float p = __expf(sreg[i][j] - mn);
                Ps[(ty + 16 * i) * 65 + tx + 16 * j] = p;
                ps += p;
            }
            #pragma unroll
            for (int o = 8; o > 0; o >>= 1)
                ps += __shfl_xor_sync(0xffffffffu, ps, o);
            l_run[i] = l_run[i] * corr + ps;
            m_run[i] = mn;
            #pragma unroll
            for (int j = 0; j < 4; j++) oacc[i][j] *= corr;
        }
        __syncthreads();

        #pragma unroll 8
        for (int c = 0; c < 64; c++) {
            float pv[8], vv[4];
            #pragma unroll
            for (int i = 0; i < 8; i++) pv[i] = Ps[(ty + 16 * i) * 65 + c];
            #pragma unroll
            for (int j = 0; j < 4; j++) vv[j] = Vs[c * 64 + tx + 16 * j];
            #pragma unroll
            for (int i = 0; i < 8; i++)
                #pragma unroll
                for (int j = 0; j < 4; j++)
                    oacc[i][j] += pv[i] * vv[j];
        }
        __syncthreads();
    }

    #pragma unroll
    for (int i = 0; i < 8; i++) {
        float inv = 1.0f / l_run[i];
        int r = q0 + ty + 16 * i;
        #pragma unroll
        for (int j = 0; j < 4; j++)
            O[base + (size_t)r * D_ + tx + 16 * j] = tf32r(oacc[i][j] * inv);
    }
}

// ---------------------------------------------------------------------------
// Launch
// ---------------------------------------------------------------------------
extern "C" void kernel_launch(void* const* d_in, const int* in_sizes, int n_in,
                              void* d_out, int out_size)
{
    (void)in_sizes; (void)n_in; (void)out_size;
    const float* x    = (const float*)d_in[0];
    const int*   lidx = (const int*)  d_in[1];
    const float* Wq = (const float*)d_in[2];  const float* bq = (const float*)d_in[3];
    const float* Wk = (const float*)d_in[4];  const float* bk = (const float*)d_in[5];
    const float* Wv = (const float*)d_in[6];  const float* bv = (const float*)d_in[7];
    const float* Wo = (const float*)d_in[8];  const float* bo = (const float*)d_in[9];
    const float* s1 = (const float*)d_in[10]; const float* b1n = (const float*)d_in[11];
    const float* s2 = (const float*)d_in[12]; const float* b2n = (const float*)d_in[13];
    const float* W1 = (const float*)d_in[14]; const float* bf1 = (const float*)d_in[15];
    const float* W2 = (const float*)d_in[16]; const float* bf2 = (const float*)d_in[17];
    float* out = (float*)d_out;

    float *h_, *q_, *k_, *v_, *at_, *ff_;
    float *wqT, *wkT, *wvT, *woT, *w1T, *w2T;
    cudaGetSymbolAddress((void**)&h_,  g_h);
    cudaGetSymbolAddress((void**)&q_,  g_q);
    cudaGetSymbolAddress((void**)&k_,  g_k);
    cudaGetSymbolAddress((void**)&v_,  g_v);
    cudaGetSymbolAddress((void**)&at_, g_attn);
    cudaGetSymbolAddress((void**)&ff_, g_ffn);
    cudaGetSymbolAddress((void**)&wqT, g_WqT);
    cudaGetSymbolAddress((void**)&wkT, g_WkT);
    cudaGetSymbolAddress((void**)&wvT, g_WvT);
    cudaGetSymbolAddress((void**)&woT, g_WoT);
    cudaGetSymbolAddress((void**)&w1T, g_W1T);
    cudaGetSymbolAddress((void**)&w2T, g_W2T);

    cudaFuncSetAttribute(attention_kernel,
                         cudaFuncAttributeMaxDynamicSharedMemorySize, AT_SMEM_BYTES);
    cudaFuncSetAttribute(gemm_mma<0,0,0>,
                         cudaFuncAttributeMaxDynamicSharedMemorySize, GEMM_SMEM);
    cudaFuncSetAttribute(gemm_mma<0,1,0>,
                         cudaFuncAttributeMaxDynamicSharedMemorySize, GEMM_SMEM);
    cudaFuncSetAttribute(gemm_mma<1,0,1>,
                         cudaFuncAttributeMaxDynamicSharedMemorySize, GEMM_SMEM);

    // Weight transpose + tf32 rounding
    dim3 tb(32, 8);
    transpose_round_kernel<<<dim3(D_/32, D_/32, L_), tb>>>(Wq, wqT, D_, D_);
    transpose_round_kernel<<<dim3(D_/32, D_/32, L_), tb>>>(Wk, wkT, D_, D_);
    transpose_round_kernel<<<dim3(D_/32, D_/32, L_), tb>>>(Wv, wvT, D_, D_);
    transpose_round_kernel<<<dim3(D_/32, D_/32, L_), tb>>>(Wo, woT, D_, D_);
    transpose_round_kernel<<<dim3(F_/32, D_/32, L_), tb>>>(W1, w1T, D_, F_);
    transpose_round_kernel<<<dim3(D_/32, F_/32, L_), tb>>>(W2, w2T, F_, D_);

    dim3 gD(D_ / 128, S_ / 128, B_);
    dim3 gF(F_ / 128, S_ / 128, B_);

    // LN1 -> h (tf32-rounded)
    ln_kernel<<<B_ * S_, 256>>>(x, s1, b1n, lidx, h_);
    // QKV (fp32 outputs for SIMT attention)
    gemm_mma<0,0,0><<<gD, 256, GEMM_SMEM>>>(h_, wqT, bq, lidx, nullptr, q_, S_, D_, D_);
    gemm_mma<0,0,0><<<gD, 256, GEMM_SMEM>>>(h_, wkT, bk, lidx, nullptr, k_, S_, D_, D_);
    gemm_mma<0,0,0><<<gD, 256, GEMM_SMEM>>>(h_, wvT, bv, lidx, nullptr, v_, S_, D_, D_);
    // Attention (tf32-rounded output -> Wo GEMM input)
    attention_kernel<<<dim3(S_ / 128, H_, B_), 256, AT_SMEM_BYTES>>>(q_, k_, v_, at_);
    // O-proj + residual(x) -> out
    gemm_mma<0,1,0><<<gD, 256, GEMM_SMEM>>>(at_, woT, bo, lidx, x, out, S_, D_, D_);
    // LN2 -> h (tf32-rounded)
    ln_kernel<<<B_ * S_, 256>>>(out, s2, b2n, lidx, h_);
    // FFN1 + GELU (tf32-rounded -> FFN2 input)
    gemm_mma<1,0,1><<<gF, 256, GEMM_SMEM>>>(h_, w1T, bf1, lidx, nullptr, ff_, S_, D_, F_);
    // FFN2 + residual(out) -> final
    gemm_mma<0,1,0><<<gD, 256, GEMM_SMEM>>>(ff_, w2T, bf2, lidx, out, out, S_, F_, D_);
}